// round 7
// baseline (speedup 1.0000x reference)
#include <cuda_runtime.h>

#define NBATCH 32
#define NN 1024
#define FILL_PER_BATCH 8                       // fill blocks per batch
#define FILL_BLOCKS (NBATCH * FILL_PER_BATCH)  // 256
#define F4_PER_BATCH (NN * NN / 4)             // 262144 float4 per batch
#define F4_PER_FILL (F4_PER_BATCH / FILL_PER_BATCH)  // 32768
#define FILL_ITERS (F4_PER_FILL / NN)          // 32

// persistent device scratch (zero-init at load). Self-resetting per invocation.
__device__ unsigned g_fill[NBATCH];

// ---------------------------------------------------------------------------
// Single-wave fused kernel: 32 sorter blocks + 256 fill blocks = 288 blocks
// of 1024 threads — all resident in ONE wave (148 SMs x 2 blocks). Fill
// blocks stream 512KB each with no block churn; sorters hide under the fill
// and patch the <=2 nonzero floats per row at the end.
// ---------------------------------------------------------------------------
__global__ void __launch_bounds__(NN, 2) fused_kernel(const float* __restrict__ x,
                                                      float* __restrict__ out) {
    const int t = threadIdx.x;

    if (blockIdx.x >= NBATCH) {
        // ======================= fill block (no waiting) ====================
        const int fb = blockIdx.x - NBATCH;      // 0 .. 255
        const int b   = fb >> 3;                 // batch
        const int sub = fb & 7;                  // sub-region within batch
        float4* out4 = (float4*)out + (size_t)b * F4_PER_BATCH
                                    + (size_t)sub * F4_PER_FILL + t;
        const float4 z = make_float4(0.0f, 0.0f, 0.0f, 0.0f);
        #pragma unroll 8
        for (int i = 0; i < FILL_ITERS; i++)
            __stcs(out4 + i * NN, z);
        __syncthreads();
        if (t == 0) {
            __threadfence();
            atomicAdd(&g_fill[b], 1u);
        }
        return;
    }

    // ======================= sorter + patcher block =========================
    __shared__ unsigned long long sA[NN];   // ping
    __shared__ unsigned long long sB[NN];   // pong
    __shared__ float thv[NN];               // original theta by index
    __shared__ float ysw[33 * 32];          // y, swizzled for conflict-free PAV
    __shared__ float cm[33 * 32];           // chunk PAV stacks: means
    __shared__ int   cc[33 * 32];           // chunk PAV stacks: counts
    __shared__ int   bn[32];                // blocks per chunk
    __shared__ float fm[NN];                // final block means
    __shared__ int   fc[NN];                // final block counts
    __shared__ int   fs[NN + 1];            // final block starts
    __shared__ int   nbF;

    const int b = blockIdx.x;
    float v = x[b * NN + t];                // eps = 1.0 -> theta = x
    thv[t] = v;

    // 64-bit key: ascending sort == descending by value, ties by index asc.
    unsigned u  = __float_as_uint(v);
    unsigned ka = u ^ ((u & 0x80000000u) ? 0xFFFFFFFFu : 0x80000000u);
    unsigned long long cur = ((unsigned long long)(~ka) << 32) | (unsigned)t;

    // ---- bitonic sort (ascending keys), 1 barrier per shared stage ----
    int pp = 0;
    for (int k = 2; k <= NN; k <<= 1) {
        const bool asc = ((t & k) == 0);
        for (int j = k >> 1; j >= 32; j >>= 1) {
            unsigned long long* buf = pp ? sB : sA;
            buf[t] = cur;
            __syncthreads();
            unsigned long long other = buf[t ^ j];
            pp ^= 1;
            bool takeMin = (((t & j) == 0) == asc);
            cur = takeMin ? (cur < other ? cur : other)
                          : (cur > other ? cur : other);
        }
        int j0 = (k >> 1) < 16 ? (k >> 1) : 16;
        for (int j = j0; j >= 1; j >>= 1) {
            unsigned long long other = __shfl_xor_sync(0xFFFFFFFFu, cur, j);
            bool takeMin = (((t & j) == 0) == asc);
            cur = takeMin ? (cur < other ? cur : other)
                          : (cur > other ? cur : other);
        }
    }

    const int   id  = (int)(cur & 0xFFFFFFFFull);   // original index at rank t
    const float s_t = thv[id];                      // sorted (descending) value

    // y[t] = s_t - (NN - t), swizzled: reader lane l, elem i -> addr i*33 + l
    ysw[(t & 31) * 33 + (t >> 5)] = s_t - (float)(NN - t);
    __syncthreads();

    // ---- chunked PAV: warp 0, lane l handles y[32l .. 32l+31] ----
    if (t < 32) {
        int   nb = 0;
        float tm = ysw[t];
        int   tc = 1;
        for (int i = 1; i < 32; i++) {
            float m = ysw[i * 33 + t];
            int   c = 1;
            while (tc > 0 && tm < m) {
                m = (tm * (float)tc + m * (float)c) / (float)(tc + c);
                c += tc;
                if (nb == 0) { tc = 0; break; }
                nb--; tm = cm[nb * 33 + t]; tc = cc[nb * 33 + t];
            }
            if (tc > 0) { cm[nb * 33 + t] = tm; cc[nb * 33 + t] = tc; nb++; }
            tm = m; tc = c;
        }
        cm[nb * 33 + t] = tm; cc[nb * 33 + t] = tc; nb++;
        bn[t] = nb;
    }
    __syncthreads();

    // ---- serial merge of the 32 chunk stacks (short) ----
    if (t == 0) {
        int   nb = 0;
        float tm = 0.0f;
        int   tc = 0;
        for (int l = 0; l < 32; l++) {
            const int cnt = bn[l];
            for (int i = 0; i < cnt; i++) {
                float m = cm[i * 33 + l];
                int   c = cc[i * 33 + l];
                if (tc == 0) { tm = m; tc = c; continue; }
                while (tc > 0 && tm < m) {
                    m = (tm * (float)tc + m * (float)c) / (float)(tc + c);
                    c += tc;
                    if (nb == 0) { tc = 0; break; }
                    nb--; tm = fm[nb]; tc = fc[nb];
                }
                if (tc > 0) { fm[nb] = tm; fc[nb] = tc; nb++; }
                tm = m; tc = c;
            }
        }
        fm[nb] = tm; fc[nb] = tc; nb++;
        int pos = 0;
        for (int q = 0; q < nb; q++) { fs[q] = pos; pos += fc[q]; }
        fs[nb] = pos;
        nbF = nb;
    }
    __syncthreads();

    // ---- rank for original row `id`: primal = s - sol ----
    float r;
    {
        int lo = 0, hi = nbF - 1;
        while (lo < hi) {
            int mid = (lo + hi + 1) >> 1;
            if (fs[mid] <= t) lo = mid; else hi = mid - 1;
        }
        r = s_t - fm[lo];
    }

    // ---- wait for this batch's 8 fill blocks, then reset + patch ----
    if (t == 0) {
        while (atomicAdd(&g_fill[b], 0u) < (unsigned)FILL_PER_BATCH)
            __nanosleep(128);
        __threadfence();                                  // acquire
        atomicSub(&g_fill[b], (unsigned)FILL_PER_BATCH);  // reset for replay
    }
    __syncthreads();

    {
        const size_t rowBase = ((size_t)b * NN + (size_t)id) * NN;
        const int t0 = (int)floorf(r);
        #pragma unroll
        for (int d = 0; d <= 1; d++) {
            int tt = t0 + d;                 // candidate target (i+1)
            if (tt >= 1 && tt <= NN) {
                float val = 1.0f - fabsf(r - (float)tt);
                if (val > 0.0f) out[rowBase + (tt - 1)] = val;
            }
        }
    }
}

extern "C" void kernel_launch(void* const* d_in, const int* in_sizes, int n_in,
                              void* d_out, int out_size) {
    const float* x = (const float*)d_in[0];
    fused_kernel<<<NBATCH + FILL_BLOCKS, NN>>>(x, (float*)d_out);
}

// round 9
// speedup vs baseline: 1.0666x; 1.0666x over previous
#include <cuda_runtime.h>

#define NBATCH 32
#define NN 1024
#define FILL_PER_BATCH 8                       // fill blocks per batch
#define FILL_BLOCKS (NBATCH * FILL_PER_BATCH)  // 256
#define BYTES_PER_FILL (NN * NN * 4 / FILL_PER_BATCH)   // 524288 (512KB)
#define STAGE_BYTES 32768                      // SMEM staging buffer
#define BULKS_PER_FILL (BYTES_PER_FILL / STAGE_BYTES)   // 16

// persistent device scratch (zero-init at load). Self-resetting per invocation.
__device__ unsigned g_fill[NBATCH];

// ---------------------------------------------------------------------------
// Single-wave fused kernel, TMA-store edition.
//  blocks [0, 32):    sorter/patcher per batch (bitonic + chunked PAV), then
//                     wait for this batch's 8 fill blocks, patch <=2 floats/row.
//  blocks [32, 288):  zero a 32KB SMEM stage once, then 16x cp.async.bulk
//                     SMEM->GMEM (512KB) via the TMA path; fence; count; exit.
// Shared memory is one manually-overlaid 46KB arena (branch-exclusive use).
// ---------------------------------------------------------------------------
__global__ void __launch_bounds__(NN, 2) fused_kernel(const float* __restrict__ x,
                                                      float* __restrict__ out) {
    __shared__ __align__(128) unsigned char shm[46592];
    const int t = threadIdx.x;

    if (blockIdx.x >= NBATCH) {
        // ======================= fill block (TMA bulk stores) ===============
        // zero the 32KB stage: 2048 float4 by 1024 threads
        float4* z4 = (float4*)shm;
        const float4 z = make_float4(0.0f, 0.0f, 0.0f, 0.0f);
        z4[t]        = z;
        z4[t + 1024] = z;
        __syncthreads();

        if (t == 0) {
            // make generic-proxy SMEM writes visible to the async proxy
            asm volatile("fence.proxy.async.shared::cta;" ::: "memory");
            unsigned saddr = (unsigned)__cvta_generic_to_shared(shm);
            const int fb = blockIdx.x - NBATCH;              // 0 .. 255
            char* dst = (char*)out + (size_t)fb * BYTES_PER_FILL;
            #pragma unroll
            for (int i = 0; i < BULKS_PER_FILL; i++) {
                asm volatile(
                    "cp.async.bulk.global.shared::cta.bulk_group [%0], [%1], %2;"
                    :: "l"(dst + (size_t)i * STAGE_BYTES), "r"(saddr),
                       "r"((int)STAGE_BYTES)
                    : "memory");
            }
            asm volatile("cp.async.bulk.commit_group;" ::: "memory");
            asm volatile("cp.async.bulk.wait_group 0;" ::: "memory");
            __threadfence();                                 // writes visible
            atomicAdd(&g_fill[fb >> 3], 1u);
        }
        return;
    }

    // ======================= sorter + patcher block =========================
    // manual overlay of the 46KB arena
    unsigned long long* sA  = (unsigned long long*)(shm);            //  8192 B
    unsigned long long* sB  = (unsigned long long*)(shm + 8192);     //  8192 B
    float*              thv = (float*)(shm + 16384);                 //  4096 B
    float*              ysw = (float*)(shm + 20480);                 //  4224 B
    float*              cm  = (float*)(shm + 24704);                 //  4224 B
    int*                cc  = (int*)  (shm + 28928);                 //  4224 B
    int*                bn  = (int*)  (shm + 33152);                 //   128 B
    float*              fm  = (float*)(shm + 33280);                 //  4096 B
    int*                fc  = (int*)  (shm + 37376);                 //  4096 B
    int*                fs  = (int*)  (shm + 41472);                 //  4100 B
    int*                nbF = (int*)  (shm + 45576);                 //     4 B

    const int b = blockIdx.x;
    float v = x[b * NN + t];                // eps = 1.0 -> theta = x
    thv[t] = v;

    // 64-bit key: ascending sort == descending by value, ties by index asc.
    unsigned u  = __float_as_uint(v);
    unsigned ka = u ^ ((u & 0x80000000u) ? 0xFFFFFFFFu : 0x80000000u);
    unsigned long long cur = ((unsigned long long)(~ka) << 32) | (unsigned)t;

    // ---- bitonic sort (ascending keys), 1 barrier per shared stage ----
    int pp = 0;
    for (int k = 2; k <= NN; k <<= 1) {
        const bool asc = ((t & k) == 0);
        for (int j = k >> 1; j >= 32; j >>= 1) {
            unsigned long long* buf = pp ? sB : sA;
            buf[t] = cur;
            __syncthreads();
            unsigned long long other = buf[t ^ j];
            pp ^= 1;
            bool takeMin = (((t & j) == 0) == asc);
            cur = takeMin ? (cur < other ? cur : other)
                          : (cur > other ? cur : other);
        }
        int j0 = (k >> 1) < 16 ? (k >> 1) : 16;
        for (int j = j0; j >= 1; j >>= 1) {
            unsigned long long other = __shfl_xor_sync(0xFFFFFFFFu, cur, j);
            bool takeMin = (((t & j) == 0) == asc);
            cur = takeMin ? (cur < other ? cur : other)
                          : (cur > other ? cur : other);
        }
    }

    const int   id  = (int)(cur & 0xFFFFFFFFull);   // original index at rank t
    const float s_t = thv[id];                      // sorted (descending) value

    // y[t] = s_t - (NN - t), swizzled: reader lane l, elem i -> addr i*33 + l
    ysw[(t & 31) * 33 + (t >> 5)] = s_t - (float)(NN - t);
    __syncthreads();

    // ---- chunked PAV: warp 0, lane l handles y[32l .. 32l+31] ----
    if (t < 32) {
        int   nb = 0;
        float tm = ysw[t];
        int   tc = 1;
        for (int i = 1; i < 32; i++) {
            float m = ysw[i * 33 + t];
            int   c = 1;
            while (tc > 0 && tm < m) {
                m = (tm * (float)tc + m * (float)c) / (float)(tc + c);
                c += tc;
                if (nb == 0) { tc = 0; break; }
                nb--; tm = cm[nb * 33 + t]; tc = cc[nb * 33 + t];
            }
            if (tc > 0) { cm[nb * 33 + t] = tm; cc[nb * 33 + t] = tc; nb++; }
            tm = m; tc = c;
        }
        cm[nb * 33 + t] = tm; cc[nb * 33 + t] = tc; nb++;
        bn[t] = nb;
    }
    __syncthreads();

    // ---- serial merge of the 32 chunk stacks (short) ----
    if (t == 0) {
        int   nb = 0;
        float tm = 0.0f;
        int   tc = 0;
        for (int l = 0; l < 32; l++) {
            const int cnt = bn[l];
            for (int i = 0; i < cnt; i++) {
                float m = cm[i * 33 + l];
                int   c = cc[i * 33 + l];
                if (tc == 0) { tm = m; tc = c; continue; }
                while (tc > 0 && tm < m) {
                    m = (tm * (float)tc + m * (float)c) / (float)(tc + c);
                    c += tc;
                    if (nb == 0) { tc = 0; break; }
                    nb--; tm = fm[nb]; tc = fc[nb];
                }
                if (tc > 0) { fm[nb] = tm; fc[nb] = tc; nb++; }
                tm = m; tc = c;
            }
        }
        fm[nb] = tm; fc[nb] = tc; nb++;
        int pos = 0;
        for (int q = 0; q < nb; q++) { fs[q] = pos; pos += fc[q]; }
        fs[nb] = pos;
        *nbF = nb;
    }
    __syncthreads();

    // ---- rank for original row `id`: primal = s - sol ----
    float r;
    {
        int lo = 0, hi = *nbF - 1;
        while (lo < hi) {
            int mid = (lo + hi + 1) >> 1;
            if (fs[mid] <= t) lo = mid; else hi = mid - 1;
        }
        r = s_t - fm[lo];
    }

    // ---- wait for this batch's 8 fill blocks, then reset + patch ----
    if (t == 0) {
        while (atomicAdd(&g_fill[b], 0u) < (unsigned)FILL_PER_BATCH)
            __nanosleep(128);
        __threadfence();                                  // acquire
        atomicSub(&g_fill[b], (unsigned)FILL_PER_BATCH);  // reset for replay
    }
    __syncthreads();

    {
        const size_t rowBase = ((size_t)b * NN + (size_t)id) * NN;
        const int t0 = (int)floorf(r);
        #pragma unroll
        for (int d = 0; d <= 1; d++) {
            int tt = t0 + d;                 // candidate target (i+1)
            if (tt >= 1 && tt <= NN) {
                float val = 1.0f - fabsf(r - (float)tt);
                if (val > 0.0f) out[rowBase + (tt - 1)] = val;
            }
        }
    }
}

extern "C" void kernel_launch(void* const* d_in, const int* in_sizes, int n_in,
                              void* d_out, int out_size) {
    const float* x = (const float*)d_in[0];
    fused_kernel<<<NBATCH + FILL_BLOCKS, NN>>>(x, (float*)d_out);
}